// round 1
// baseline (speedup 1.0000x reference)
#include <cuda_runtime.h>
#include <math.h>

// Problem constants
#define Bc 64
#define Tc 128
#define Dc 1024
#define Hc 512
#define Gc 2048            // 4*H
#define Jc 126             // T-2
#define MU 8192            // B*T  (rows of U; t=127 row unused but keeps tiles even)
#define M2 8064            // B*J  (= 63*128)

// Scratch (device globals: allocation-free per harness rules)
__device__ float g_U [(size_t)MU * Gc];   // x @ W_ih^T  (shared by both LSTM steps)
__device__ float g_G2[(size_t)M2 * Gc];   // h1 @ W_hh^T
__device__ float g_h1[(size_t)M2 * Hc];
__device__ float g_c1[(size_t)M2 * Hc];
__device__ float g_xs[MU];
__device__ float g_hs[M2];
__device__ float g_partial[2 * Bc];

__device__ __forceinline__ float sigf(float x) { return 1.f / (1.f + expf(-x)); }

// ---------------------------------------------------------------------------
// SGEMM (NT): C[m,n] = sum_k A[m,k] * W[n,k].  A,W row-major K-contiguous.
// MODE 0: A = ext (encoder_output), C = g_U, K = 1024
// MODE 1: A = g_h1,                 C = g_G2, K = 512
// 128x128 block tile, BK=16, 256 threads, 8x8 per thread.
// ---------------------------------------------------------------------------
#define BM 128
#define BN 128
#define BK 16
#define TM 8
#define TN 8

template <int MODE>
__global__ __launch_bounds__(256) void sgemm_nt(const float* __restrict__ Aext,
                                                const float* __restrict__ W,
                                                int K) {
    const float* A = (MODE == 0) ? Aext : g_h1;
    float*       C = (MODE == 0) ? g_U  : g_G2;

    __shared__ __align__(16) float As[BK][BM + 4];
    __shared__ __align__(16) float Ws[BK][BN + 4];

    const int tid = threadIdx.x;
    const int tx = tid & 15;        // 0..15 (N dir)
    const int ty = tid >> 4;        // 0..15 (M dir)
    const int lr = tid >> 2;        // 0..63 load row base
    const int lc = (tid & 3) << 2;  // 0,4,8,12 load col

    const float* Ab = A + (size_t)blockIdx.y * BM * K;
    const float* Wb = W + (size_t)blockIdx.x * BN * K;

    float acc[TM][TN];
#pragma unroll
    for (int i = 0; i < TM; i++)
#pragma unroll
        for (int j = 0; j < TN; j++) acc[i][j] = 0.f;

    for (int k0 = 0; k0 < K; k0 += BK) {
#pragma unroll
        for (int s = 0; s < 2; s++) {
            int row = lr + s * 64;
            float4 va = *(const float4*)(Ab + (size_t)row * K + k0 + lc);
            As[lc + 0][row] = va.x; As[lc + 1][row] = va.y;
            As[lc + 2][row] = va.z; As[lc + 3][row] = va.w;
            float4 vw = *(const float4*)(Wb + (size_t)row * K + k0 + lc);
            Ws[lc + 0][row] = vw.x; Ws[lc + 1][row] = vw.y;
            Ws[lc + 2][row] = vw.z; Ws[lc + 3][row] = vw.w;
        }
        __syncthreads();
#pragma unroll
        for (int kk = 0; kk < BK; kk++) {
            float a[TM], bb[TN];
            *(float4*)&a[0]  = *(const float4*)&As[kk][ty * TM];
            *(float4*)&a[4]  = *(const float4*)&As[kk][ty * TM + 4];
            *(float4*)&bb[0] = *(const float4*)&Ws[kk][tx * TN];
            *(float4*)&bb[4] = *(const float4*)&Ws[kk][tx * TN + 4];
#pragma unroll
            for (int i = 0; i < TM; i++)
#pragma unroll
                for (int j = 0; j < TN; j++)
                    acc[i][j] = fmaf(a[i], bb[j], acc[i][j]);
        }
        __syncthreads();
    }

    float* Cb = C + (size_t)(blockIdx.y * BM + ty * TM) * Gc + blockIdx.x * BN + tx * TN;
#pragma unroll
    for (int i = 0; i < TM; i++) {
        *(float4*)(Cb + (size_t)i * Gc)     = make_float4(acc[i][0], acc[i][1], acc[i][2], acc[i][3]);
        *(float4*)(Cb + (size_t)i * Gc + 4) = make_float4(acc[i][4], acc[i][5], acc[i][6], acc[i][7]);
    }
}

// ---------------------------------------------------------------------------
// LSTM step 1 gates: h,c from zero state.  c1 = sig(i)*tanh(g); h1 = sig(o)*tanh(c1)
// ---------------------------------------------------------------------------
__global__ __launch_bounds__(256) void gates1_kernel(const float* __restrict__ b_ih,
                                                     const float* __restrict__ b_hh) {
    int idx = blockIdx.x * blockDim.x + threadIdx.x;
    if (idx >= M2 * Hc) return;
    int h  = idx & (Hc - 1);
    int m2 = idx >> 9;
    int j  = m2 % Jc;
    int b  = m2 / Jc;
    const float* u = g_U + (size_t)(b * Tc + j) * Gc;
    float gi = u[h]            + b_ih[h]            + b_hh[h];
    float gg = u[2 * Hc + h]   + b_ih[2 * Hc + h]   + b_hh[2 * Hc + h];
    float go = u[3 * Hc + h]   + b_ih[3 * Hc + h]   + b_hh[3 * Hc + h];
    float c  = sigf(gi) * tanhf(gg);
    g_c1[idx] = c;
    g_h1[idx] = sigf(go) * tanhf(c);
}

// ---------------------------------------------------------------------------
// LSTM step 2 gates + hs = h2 . w_h  (one block per (b,j), 512 threads)
// ---------------------------------------------------------------------------
__global__ __launch_bounds__(512) void gates2_kernel(const float* __restrict__ b_ih,
                                                     const float* __restrict__ b_hh,
                                                     const float* __restrict__ fc_w) {
    int m2 = blockIdx.x;
    int h  = threadIdx.x;
    int j  = m2 % Jc, b = m2 / Jc;
    const float* g2 = g_G2 + (size_t)m2 * Gc;
    const float* u  = g_U + (size_t)(b * Tc + j + 1) * Gc;
    float gi = g2[h]          + u[h]          + b_ih[h]          + b_hh[h];
    float gf = g2[Hc + h]     + u[Hc + h]     + b_ih[Hc + h]     + b_hh[Hc + h];
    float gg = g2[2 * Hc + h] + u[2 * Hc + h] + b_ih[2 * Hc + h] + b_hh[2 * Hc + h];
    float go = g2[3 * Hc + h] + u[3 * Hc + h] + b_ih[3 * Hc + h] + b_hh[3 * Hc + h];
    float c  = sigf(gf) * g_c1[(size_t)m2 * Hc + h] + sigf(gi) * tanhf(gg);
    float h2 = sigf(go) * tanhf(c);

    __shared__ float red[512];
    red[h] = h2 * fc_w[h];   // fc_w[:H] = w_h
    __syncthreads();
    for (int s = 256; s > 0; s >>= 1) {
        if (h < s) red[h] += red[h + s];
        __syncthreads();
    }
    if (h == 0) g_hs[m2] = red[0];
}

// ---------------------------------------------------------------------------
// xs[b,t] = x[b,t] . w_x   (one block per row)
// ---------------------------------------------------------------------------
__global__ __launch_bounds__(256) void xs_kernel(const float* __restrict__ x,
                                                 const float* __restrict__ fc_w) {
    int row = blockIdx.x;
    const float* xr = x + (size_t)row * Dc;
    const float* wx = fc_w + Hc;
    float s = 0.f;
    for (int k = threadIdx.x; k < Dc; k += 256) s += xr[k] * wx[k];
    __shared__ float red[256];
    red[threadIdx.x] = s;
    __syncthreads();
    for (int t = 128; t > 0; t >>= 1) {
        if (threadIdx.x < t) red[threadIdx.x] += red[threadIdx.x + t];
        __syncthreads();
    }
    if (threadIdx.x == 0) g_xs[row] = red[0];
}

// ---------------------------------------------------------------------------
// Per-batch loss: online LSE over candidates.  One block per b, 8 warps.
// Invalid candidates (-1e9 in reference) underflow exp() to exactly 0, so
// skipping them is bit-equivalent to the reference masking.
// ---------------------------------------------------------------------------
__global__ __launch_bounds__(256) void loss_kernel(const int* __restrict__ mask,
                                                   const float* __restrict__ fcb_p) {
    int b = blockIdx.x;
    int tid = threadIdx.x;
    __shared__ int redi[256];
    __shared__ int s_len;
    __shared__ float wacc[8];

    int mv = (tid < Tc) ? mask[b * Tc + tid] : 0;
    redi[tid] = mv;
    __syncthreads();
    for (int s = 128; s > 0; s >>= 1) {
        if (tid < s) redi[tid] += redi[tid + s];
        __syncthreads();
    }
    if (tid == 0) s_len = redi[0];
    __syncthreads();
    int len = s_len;
    float fcb = fcb_p[0];

    int warp = tid >> 5, lane = tid & 31;
    float wsum = 0.f;
    for (int j = warp; j < Jc; j += 8) {
        int rlim = len - j - 2;          // # valid candidates; row valid iff >=1
        if (rlim <= 0) continue;         // uniform across warp
        if (rlim > Jc) rlim = Jc;
        float hv = g_hs[b * Jc + j];
        float m = -1e30f, ssum = 0.f;
        for (int r = lane; r < rlim; r += 32) {
            float lg = hv + g_xs[b * Tc + j + 2 + r] + fcb;
            if (lg > m) { ssum = ssum * expf(m - lg) + 1.f; m = lg; }
            else        { ssum += expf(lg - m); }
        }
        for (int off = 16; off; off >>= 1) {
            float m2v = __shfl_xor_sync(0xffffffffu, m, off);
            float s2v = __shfl_xor_sync(0xffffffffu, ssum, off);
            float M = fmaxf(m, m2v);
            ssum = ssum * expf(m - M) + s2v * expf(m2v - M);
            m = M;
        }
        float lse    = m + logf(ssum);
        float logit0 = hv + g_xs[b * Tc + j + 2] + fcb;
        wsum += lse - logit0;
    }
    if (lane == 0) wacc[warp] = wsum;
    __syncthreads();
    if (tid == 0) {
        float tot = 0.f;
        for (int w = 0; w < 8; w++) tot += wacc[w];
        int cnt = len - 2;
        if (cnt < 0) cnt = 0;
        if (cnt > Jc) cnt = Jc;
        g_partial[2 * b]     = tot;
        g_partial[2 * b + 1] = (float)cnt;
    }
}

__global__ void final_kernel(float* __restrict__ out) {
    float tot = 0.f, cnt = 0.f;
    for (int b = 0; b < Bc; b++) {
        tot += g_partial[2 * b];
        cnt += g_partial[2 * b + 1];
    }
    out[0] = (cnt > 0.f) ? tot / cnt : 0.f;
}

// ---------------------------------------------------------------------------
extern "C" void kernel_launch(void* const* d_in, const int* in_sizes, int n_in,
                              void* d_out, int out_size) {
    const float* x    = (const float*)d_in[0];
    const int*   mask = (const int*)d_in[1];
    const float* W_ih = (const float*)d_in[2];
    const float* W_hh = (const float*)d_in[3];
    const float* b_ih = (const float*)d_in[4];
    const float* b_hh = (const float*)d_in[5];
    const float* fc_w = (const float*)d_in[6];
    const float* fc_b = (const float*)d_in[7];
    float* out = (float*)d_out;

    // GEMM1: U = x @ W_ih^T  (M=8192, N=2048, K=1024) — shared by both LSTM steps
    dim3 grid1(Gc / BN, MU / BM);
    sgemm_nt<0><<<grid1, 256>>>(x, W_ih, Dc);

    // Step-1 gates
    int n1 = M2 * Hc;
    gates1_kernel<<<(n1 + 255) / 256, 256>>>(b_ih, b_hh);

    // GEMM2: G2 = h1 @ W_hh^T  (M=8064, N=2048, K=512)
    dim3 grid2(Gc / BN, M2 / BM);
    sgemm_nt<1><<<grid2, 256>>>(nullptr, W_hh, Hc);

    // Step-2 gates + hs dot
    gates2_kernel<<<M2, 512>>>(b_ih, b_hh, fc_w);

    // xs projections
    xs_kernel<<<MU, 256>>>(x, fc_w);

    // Loss per batch + final deterministic reduction
    loss_kernel<<<Bc, 256>>>(mask, fc_b);
    final_kernel<<<1, 1>>>(out);
}

// round 3
// speedup vs baseline: 51.9403x; 51.9403x over previous
#include <cuda_runtime.h>
#include <math.h>

// Problem constants
#define Bc 64
#define Tc 128
#define Dc 1024
#define Jc 126             // T-2
#define MU 8192            // B*T rows of xs

// Scratch (device globals: allocation-free per harness rules)
__device__ float g_xs[MU];
__device__ float g_partial[2 * Bc];

// ---------------------------------------------------------------------------
// xs[b,t] = x[b,t] . w_x   (one block per row, 256 threads, 1 float4 each)
// w_x = fc_w[H:]  (H = 512)
// ---------------------------------------------------------------------------
__global__ __launch_bounds__(256) void xs_kernel(const float* __restrict__ x,
                                                 const float* __restrict__ fc_w) {
    const int row = blockIdx.x;
    const int tid = threadIdx.x;
    const float4* xr = (const float4*)(x + (size_t)row * Dc);
    const float4* wx = (const float4*)(fc_w + 512);

    float4 a = xr[tid];
    float4 w = wx[tid];
    float s = a.x * w.x + a.y * w.y + a.z * w.z + a.w * w.w;

    // warp reduce
#pragma unroll
    for (int off = 16; off; off >>= 1)
        s += __shfl_xor_sync(0xffffffffu, s, off);

    __shared__ float wsum[8];
    const int lane = tid & 31, warp = tid >> 5;
    if (lane == 0) wsum[warp] = s;
    __syncthreads();
    if (tid == 0) {
        float t = 0.f;
#pragma unroll
        for (int wgt = 0; wgt < 8; wgt++) t += wsum[wgt];
        g_xs[row] = t;
    }
}

// ---------------------------------------------------------------------------
// Per-batch loss: for each valid row j (j+3 <= len):
//   loss_row = LSE_{r=0..len-j-3}( xs[b, j+2+r] ) - xs[b, j+2]
// (hs and fc_b cancel exactly along the softmax axis; masked candidates
//  are -1e9 in the reference -> exp underflows to 0 -> equivalent to skip.)
// One block per b, 8 warps; each warp owns rows j = warp, warp+8, ...
// ---------------------------------------------------------------------------
__global__ __launch_bounds__(256) void loss_kernel(const int* __restrict__ mask) {
    const int b = blockIdx.x;
    const int tid = threadIdx.x;
    const int warp = tid >> 5, lane = tid & 31;

    __shared__ float s_xs[Tc];
    __shared__ int redi[256];
    __shared__ int s_len;
    __shared__ float wacc[8];

    // load this batch's xs into smem
    if (tid < Tc) s_xs[tid] = g_xs[b * Tc + tid];

    // lengths[b] = sum(mask[b, :])
    int mv = (tid < Tc) ? mask[b * Tc + tid] : 0;
    redi[tid] = mv;
    __syncthreads();
    for (int s = 128; s > 0; s >>= 1) {
        if (tid < s) redi[tid] += redi[tid + s];
        __syncthreads();
    }
    if (tid == 0) s_len = redi[0];
    __syncthreads();
    const int len = s_len;

    float wsum = 0.f;
    for (int j = warp; j < Jc; j += 8) {
        const int rlim = len - j - 2;     // # valid candidates; row valid iff >= 1
        if (rlim <= 0) continue;          // uniform across warp
        float m = -1e30f, ssum = 0.f;
        for (int r = lane; r < rlim; r += 32) {
            float lg = s_xs[j + 2 + r];
            if (lg > m) { ssum = ssum * expf(m - lg) + 1.f; m = lg; }
            else        { ssum += expf(lg - m); }
        }
#pragma unroll
        for (int off = 16; off; off >>= 1) {
            float m2 = __shfl_xor_sync(0xffffffffu, m, off);
            float s2 = __shfl_xor_sync(0xffffffffu, ssum, off);
            float M = fmaxf(m, m2);
            ssum = ssum * expf(m - M) + s2 * expf(m2 - M);
            m = M;
        }
        wsum += (m + logf(ssum)) - s_xs[j + 2];
    }
    if (lane == 0) wacc[warp] = wsum;
    __syncthreads();
    if (tid == 0) {
        float tot = 0.f;
#pragma unroll
        for (int w = 0; w < 8; w++) tot += wacc[w];
        int cnt = len - 2;                 // # valid rows (len >= 3 guaranteed)
        if (cnt < 0) cnt = 0;
        g_partial[2 * b]     = tot;
        g_partial[2 * b + 1] = (float)cnt;
    }
}

__global__ void final_kernel(float* __restrict__ out) {
    float tot = 0.f, cnt = 0.f;
#pragma unroll
    for (int b = 0; b < Bc; b++) {
        tot += g_partial[2 * b];
        cnt += g_partial[2 * b + 1];
    }
    out[0] = (cnt > 0.f) ? tot / cnt : 0.f;
}

// ---------------------------------------------------------------------------
extern "C" void kernel_launch(void* const* d_in, const int* in_sizes, int n_in,
                              void* d_out, int out_size) {
    const float* x    = (const float*)d_in[0];
    const int*   mask = (const int*)d_in[1];
    // d_in[2..5]: W_ih, W_hh, b_ih, b_hh — unused: the LSTM head contribution
    // (hs + fc_b) is constant along the logsumexp axis and cancels exactly.
    const float* fc_w = (const float*)d_in[6];
    float* out = (float*)d_out;

    xs_kernel<<<MU, 256>>>(x, fc_w);
    loss_kernel<<<Bc, 256>>>(mask);
    final_kernel<<<1, 1>>>(out);
}

// round 4
// speedup vs baseline: 52.0125x; 1.0014x over previous
#include <cuda_runtime.h>
#include <math.h>

// Problem constants
#define Bc 64
#define Tc 128
#define Dc 1024
#define Jc 126             // T-2
#define MU 8192            // B*T rows of xs

#define ROWS_PER_BLK 8

// Scratch (device globals: allocation-free per harness rules)
__device__ float g_xs[MU];

// ---------------------------------------------------------------------------
// xs[b,t] = x[b,t] . w_x  (w_x = fc_w[512:])
// Grid 1024, block 256. Each block does 8 rows; each thread issues 8
// independent float4 loads (MLP=8+) before any reduction -> DRAM-latency
// hidden, bandwidth-bound.
// ---------------------------------------------------------------------------
__global__ __launch_bounds__(256) void xs_kernel(const float* __restrict__ x,
                                                 const float* __restrict__ fc_w) {
    const int tid = threadIdx.x;
    const int r0  = blockIdx.x * ROWS_PER_BLK;
    const float4* xb = (const float4*)(x + (size_t)r0 * Dc);
    const float4  w  = ((const float4*)(fc_w + 512))[tid];

    float4 a[ROWS_PER_BLK];
#pragma unroll
    for (int i = 0; i < ROWS_PER_BLK; i++)
        a[i] = xb[i * 256 + tid];             // 8 independent LDG.128 in flight

    float s[ROWS_PER_BLK];
#pragma unroll
    for (int i = 0; i < ROWS_PER_BLK; i++)
        s[i] = a[i].x * w.x + a[i].y * w.y + a[i].z * w.z + a[i].w * w.w;

    // warp reduction of all 8 partial rows
#pragma unroll
    for (int off = 16; off; off >>= 1)
#pragma unroll
        for (int i = 0; i < ROWS_PER_BLK; i++)
            s[i] += __shfl_xor_sync(0xffffffffu, s[i], off);

    __shared__ float wsum[8][ROWS_PER_BLK];
    const int lane = tid & 31, warp = tid >> 5;
    if (lane == 0) {
#pragma unroll
        for (int i = 0; i < ROWS_PER_BLK; i++) wsum[warp][i] = s[i];
    }
    __syncthreads();
    if (tid < ROWS_PER_BLK) {
        float t = 0.f;
#pragma unroll
        for (int k = 0; k < 8; k++) t += wsum[k][tid];
        g_xs[r0 + tid] = t;
    }
}

// ---------------------------------------------------------------------------
// Fused loss + final reduction, ONE block.
// Per batch b, per valid row j (j <= len-3):
//   loss_row = LSE( xs[b, j+2 .. len-1] ) - xs[b, j+2]
// The LSE windows are suffixes, so a single backward running-max scan gives
// every row in O(T): m,s updated with one new element per step.
// One thread per batch; then a fixed-order reduction over the 64 batches.
// (hs and fc_b cancel exactly along the softmax axis -> LSTM is dead code.)
// ---------------------------------------------------------------------------
__global__ __launch_bounds__(256) void loss_fused_kernel(const int* __restrict__ mask,
                                                         float* __restrict__ out) {
    const int tid = threadIdx.x;
    __shared__ float s_xs[Bc][Tc + 1];     // +1 pad: scan reads stride-129 -> conflict-free
    __shared__ int   s_lred[256];
    __shared__ int   s_len[Bc];
    __shared__ float s_tot[Bc];
    __shared__ float s_cnt[Bc];

    // Load all xs (8192 floats) into smem
    for (int idx = tid; idx < MU; idx += 256)
        s_xs[idx >> 7][idx & 127] = g_xs[idx];

    // lengths[b] = sum(mask[b,:]) : 4 threads per batch, 32 ints each
    {
        const int b = tid >> 2, q = tid & 3;
        const int* mb = mask + b * Tc + q * 32;
        int p = 0;
#pragma unroll
        for (int k = 0; k < 32; k += 4)
            p += mb[k] + mb[k + 1] + mb[k + 2] + mb[k + 3];
        s_lred[tid] = p;
    }
    __syncthreads();
    if ((tid & 3) == 0)
        s_len[tid >> 2] = s_lred[tid] + s_lred[tid + 1] + s_lred[tid + 2] + s_lred[tid + 3];
    __syncthreads();

    // Backward suffix scan, one thread per batch
    if (tid < Bc) {
        const int len = s_len[tid];
        const float* xr = s_xs[tid];
        float m = -1e30f, s = 0.f, tot = 0.f;
        for (int j = len - 3; j >= 0; j--) {
            const float v = xr[j + 2];
            const float nm = fmaxf(m, v);
            s = s * expf(m - nm) + expf(v - nm);
            m = nm;
            tot += (m + logf(s)) - v;
        }
        int cnt = len - 2;
        if (cnt < 0) cnt = 0;
        s_tot[tid] = tot;
        s_cnt[tid] = (float)cnt;
    }
    __syncthreads();

    if (tid == 0) {
        float tot = 0.f, cnt = 0.f;
#pragma unroll
        for (int b = 0; b < Bc; b++) { tot += s_tot[b]; cnt += s_cnt[b]; }
        out[0] = (cnt > 0.f) ? tot / cnt : 0.f;
    }
}

// ---------------------------------------------------------------------------
extern "C" void kernel_launch(void* const* d_in, const int* in_sizes, int n_in,
                              void* d_out, int out_size) {
    const float* x    = (const float*)d_in[0];
    const int*   mask = (const int*)d_in[1];
    // d_in[2..5] (W_ih, W_hh, b_ih, b_hh) and fc_b are dead: the LSTM head
    // contribution is constant along the logsumexp axis and cancels exactly.
    const float* fc_w = (const float*)d_in[6];
    float* out = (float*)d_out;

    xs_kernel<<<MU / ROWS_PER_BLK, 256>>>(x, fc_w);
    loss_fused_kernel<<<1, 256>>>(mask, out);
}

// round 5
// speedup vs baseline: 80.5970x; 1.5496x over previous
#include <cuda_runtime.h>
#include <math.h>

// Problem constants
#define Bc 64
#define Tc 128
#define Dc 1024
#define MU 8192            // B*T rows of xs

#define ROWS_PER_BLK 8

// Scratch (device globals: allocation-free per harness rules)
__device__ float g_xs[MU];
__device__ float g_partial[2 * Bc];
__device__ unsigned int g_done;    // zero-initialized at module load; reset each run

// ---------------------------------------------------------------------------
// xs[b,t] = x[b,t] . w_x  (w_x = fc_w[512:])
// Grid 1024, block 256; 8 rows/block; 8 independent LDG.128 per thread (MLP=8)
// -> DRAM-latency hidden, ~LTS-cap bound (~3.5us measured).
// ---------------------------------------------------------------------------
__global__ __launch_bounds__(256) void xs_kernel(const float* __restrict__ x,
                                                 const float* __restrict__ fc_w) {
    const int tid = threadIdx.x;
    const int r0  = blockIdx.x * ROWS_PER_BLK;
    const float4* xb = (const float4*)(x + (size_t)r0 * Dc);
    const float4  w  = ((const float4*)(fc_w + 512))[tid];

    float4 a[ROWS_PER_BLK];
#pragma unroll
    for (int i = 0; i < ROWS_PER_BLK; i++)
        a[i] = xb[i * 256 + tid];

    float s[ROWS_PER_BLK];
#pragma unroll
    for (int i = 0; i < ROWS_PER_BLK; i++)
        s[i] = a[i].x * w.x + a[i].y * w.y + a[i].z * w.z + a[i].w * w.w;

#pragma unroll
    for (int off = 16; off; off >>= 1)
#pragma unroll
        for (int i = 0; i < ROWS_PER_BLK; i++)
            s[i] += __shfl_xor_sync(0xffffffffu, s[i], off);

    __shared__ float wsum[8][ROWS_PER_BLK];
    const int lane = tid & 31, warp = tid >> 5;
    if (lane == 0) {
#pragma unroll
        for (int i = 0; i < ROWS_PER_BLK; i++) wsum[warp][i] = s[i];
    }
    __syncthreads();
    if (tid < ROWS_PER_BLK) {
        float t = 0.f;
#pragma unroll
        for (int k = 0; k < 8; k++) t += wsum[k][tid];
        g_xs[r0 + tid] = t;
    }
}

// ---------------------------------------------------------------------------
// Warp-parallel suffix-LSE loss. One warp per batch; 2 CTAs x 1024 threads.
// Suffix windows: loss_row(j) = LSE(xs[b, j+2 .. len-1]) - xs[b, j+2].
// Pair (m,s) combine is associative: (m1,s1)+(m2,s2) =
//   (max, s_hi + s_lo * exp(m_lo - m_hi)).  Identity = (-1e30, 0).
// Masked elements enter as (-1e30, 1): exp(-1e30 - m_real) == 0 exactly,
// so they contribute nothing to any valid row.  Scan runs chunk 3 -> 0
// (32 lanes each, shfl_down suffix scan), carry chained between chunks.
// Last CTA (atomic counter) does the deterministic 64-way final sum.
// ---------------------------------------------------------------------------
__device__ __forceinline__ void lse_combine(float& m, float& s, float m2, float s2) {
    const float M  = fmaxf(m, m2);
    const float lo = fminf(m, m2);
    const float e  = __expf(lo - M);
    const float shi = (m >= m2) ? s : s2;
    const float slo = (m >= m2) ? s2 : s;
    s = fmaf(slo, e, shi);
    m = M;
}

__global__ __launch_bounds__(1024) void loss_kernel(const int* __restrict__ mask,
                                                    float* __restrict__ out) {
    const int tid  = threadIdx.x;
    const int lane = tid & 31;
    const int warp = tid >> 5;
    const int b    = blockIdx.x * 32 + warp;

    // lengths[b]: 128 ints, int4 per lane
    const int4 mv = ((const int4*)(mask + b * Tc))[lane];
    int len = mv.x + mv.y + mv.z + mv.w;
#pragma unroll
    for (int off = 16; off; off >>= 1)
        len += __shfl_xor_sync(0xffffffffu, len, off);

    // load this batch's xs: 4 chunks of 32
    float v[4];
#pragma unroll
    for (int c = 0; c < 4; c++)
        v[c] = g_xs[b * Tc + c * 32 + lane];

    float mc = -1e30f, sc = 0.f;    // carry: suffix aggregate of later chunks
    float acc = 0.f;

#pragma unroll
    for (int c = 3; c >= 0; c--) {
        const int t = c * 32 + lane;
        const float vm = (t < len) ? v[c] : -1e30f;
        float m = vm, s = 1.f;
        // suffix scan within chunk (lane i aggregates elements i..31)
#pragma unroll
        for (int off = 1; off < 32; off <<= 1) {
            float m2 = __shfl_down_sync(0xffffffffu, m, off);
            float s2 = __shfl_down_sync(0xffffffffu, s, off);
            const bool ok = (lane + off) < 32;
            m2 = ok ? m2 : -1e30f;
            s2 = ok ? s2 : 0.f;
            lse_combine(m, s, m2, s2);
        }
        // fold in suffix of later chunks
        lse_combine(m, s, mc, sc);
        // row j = t - 2 valid iff t >= 2 and t <= len-1
        if (t >= 2 && t < len)
            acc += (m + __logf(s)) - vm;
        // new carry = lane 0's aggregate (this chunk + later)
        mc = __shfl_sync(0xffffffffu, m, 0);
        sc = __shfl_sync(0xffffffffu, s, 0);
    }

    // warp-reduce acc (fixed order -> deterministic)
#pragma unroll
    for (int off = 16; off; off >>= 1)
        acc += __shfl_xor_sync(0xffffffffu, acc, off);

    if (lane == 0) {
        int cnt = len - 2;
        if (cnt < 0) cnt = 0;
        g_partial[2 * b]     = acc;
        g_partial[2 * b + 1] = (float)cnt;
    }
    __syncthreads();

    // last-block-done final reduction (no extra launch)
    __shared__ unsigned int s_last;
    if (tid == 0) {
        __threadfence();
        s_last = atomicAdd(&g_done, 1u);
    }
    __syncthreads();
    if (s_last == gridDim.x - 1 && tid == 0) {
        __threadfence();
        float tot = 0.f, cnt = 0.f;
#pragma unroll
        for (int k = 0; k < Bc; k++) {
            tot += g_partial[2 * k];
            cnt += g_partial[2 * k + 1];
        }
        out[0] = (cnt > 0.f) ? tot / cnt : 0.f;
        g_done = 0;                    // reset for next graph replay
    }
}

// ---------------------------------------------------------------------------
extern "C" void kernel_launch(void* const* d_in, const int* in_sizes, int n_in,
                              void* d_out, int out_size) {
    const float* x    = (const float*)d_in[0];
    const int*   mask = (const int*)d_in[1];
    // d_in[2..5] (W_ih, W_hh, b_ih, b_hh) and fc_b are dead: the LSTM head
    // contribution is constant along the logsumexp axis and cancels exactly.
    const float* fc_w = (const float*)d_in[6];
    float* out = (float*)d_out;

    xs_kernel<<<MU / ROWS_PER_BLK, 256>>>(x, fc_w);
    loss_kernel<<<2, 1024>>>(mask, out);
}

// round 6
// speedup vs baseline: 93.4925x; 1.1600x over previous
#include <cuda_runtime.h>
#include <math.h>

// Problem constants
#define Bc 64
#define Tc 128
#define Dc 1024
#define MU 8192            // B*T rows of xs

// Scratch (device globals: allocation-free per harness rules)
__device__ float g_xs[MU];
__device__ unsigned int g_done;   // zero at load; reset by last block each run

// ---------------------------------------------------------------------------
// Fused: xs[b,t] = x[b,t].w_x  (grid 256 x 1024 thr, one warp per row,
// 8 independent LDG.128 per lane) + last-done block computes the whole loss.
//
// Loss math (LSTM head cancels along the softmax axis -> dead code):
//   loss_row(j) = log( sum_{t=j+2}^{len-1} exp(xs_t - M) ) + M - xs_{j+2}
// with M = per-batch max (constant shift; xs is O(1) so no overflow anyway).
// Suffix sums computed by warp shfl_down suffix scan (pure FADD chain).
// ---------------------------------------------------------------------------
__global__ __launch_bounds__(1024) void fused_kernel(const float* __restrict__ x,
                                                     const float* __restrict__ fc_w,
                                                     const int* __restrict__ mask,
                                                     float* __restrict__ out) {
    const int tid  = threadIdx.x;
    const int lane = tid & 31;
    const int warp = tid >> 5;

    // ---- Phase 1: xs for 32 rows (one per warp) ----
    const int row = blockIdx.x * 32 + warp;
    const float4* xr = (const float4*)(x + (size_t)row * Dc);
    const float4* wx = (const float4*)(fc_w + 512);

    float4 a[8], w[8];
#pragma unroll
    for (int i = 0; i < 8; i++) a[i] = xr[i * 32 + lane];   // 8 LDG.128 in flight
#pragma unroll
    for (int i = 0; i < 8; i++) w[i] = wx[i * 32 + lane];   // L2/L1-resident

    float s = 0.f;
#pragma unroll
    for (int i = 0; i < 8; i++)
        s += a[i].x * w[i].x + a[i].y * w[i].y + a[i].z * w[i].z + a[i].w * w[i].w;

#pragma unroll
    for (int off = 16; off; off >>= 1)
        s += __shfl_xor_sync(0xffffffffu, s, off);
    if (lane == 0) g_xs[row] = s;

    // ---- elect last block ----
    __shared__ unsigned int s_last;
    __threadfence();
    __syncthreads();
    if (tid == 0) s_last = atomicAdd(&g_done, 1u);
    __syncthreads();
    if (s_last != gridDim.x - 1) return;
    __threadfence();

    // ---- Phase 2: loss, 32 warps x 2 batches each ----
    __shared__ float s_tot[32];
    __shared__ float s_cnt[32];

    float acc = 0.f;
    float cntf = 0.f;

#pragma unroll
    for (int half = 0; half < 2; half++) {
        const int b = warp + half * 32;

        // len = sum(mask[b,:]) : int4 per lane
        const int4 mv = ((const int4*)(mask + b * Tc))[lane];
        int len = mv.x + mv.y + mv.z + mv.w;
#pragma unroll
        for (int off = 16; off; off >>= 1)
            len += __shfl_xor_sync(0xffffffffu, len, off);

        // xs row: 4 chunks of 32
        float v[4];
#pragma unroll
        for (int c = 0; c < 4; c++)
            v[c] = g_xs[b * Tc + c * 32 + lane];

        // per-batch max (over full row; valid as a constant shift)
        float M = fmaxf(fmaxf(v[0], v[1]), fmaxf(v[2], v[3]));
#pragma unroll
        for (int off = 16; off; off >>= 1)
            M = fmaxf(M, __shfl_xor_sync(0xffffffffu, M, off));

        // masked exponentials
        float e[4];
#pragma unroll
        for (int c = 0; c < 4; c++) {
            const int t = c * 32 + lane;
            e[c] = (t < len) ? __expf(v[c] - M) : 0.f;
        }

        // suffix-sum scan, chunk 3 -> 0, carry = sum of later chunks
        float carry = 0.f;
#pragma unroll
        for (int c = 3; c >= 0; c--) {
            float ss = e[c];
#pragma unroll
            for (int off = 1; off < 32; off <<= 1) {
                float s2 = __shfl_down_sync(0xffffffffu, ss, off);
                ss += ((lane + off) < 32) ? s2 : 0.f;
            }
            ss += carry;
            const int t = c * 32 + lane;
            if (t >= 2 && t < len)
                acc += __logf(ss) + M - v[c];
            carry = __shfl_sync(0xffffffffu, ss, 0);
        }

        if (lane == 0) {
            int cnt = len - 2;
            if (cnt < 0) cnt = 0;
            cntf += (float)cnt;
        }
    }

    // warp-reduce acc (fixed order)
#pragma unroll
    for (int off = 16; off; off >>= 1)
        acc += __shfl_xor_sync(0xffffffffu, acc, off);

    if (lane == 0) { s_tot[warp] = acc; s_cnt[warp] = cntf; }
    __syncthreads();

    if (tid == 0) {
        float tot = 0.f, cnt = 0.f;
#pragma unroll
        for (int k = 0; k < 32; k++) { tot += s_tot[k]; cnt += s_cnt[k]; }
        out[0] = (cnt > 0.f) ? tot / cnt : 0.f;
        g_done = 0;                      // reset for next graph replay
    }
}

// ---------------------------------------------------------------------------
extern "C" void kernel_launch(void* const* d_in, const int* in_sizes, int n_in,
                              void* d_out, int out_size) {
    const float* x    = (const float*)d_in[0];
    const int*   mask = (const int*)d_in[1];
    // d_in[2..5] (W_ih, W_hh, b_ih, b_hh) and fc_b are dead: the LSTM head
    // contribution is constant along the logsumexp axis and cancels exactly.
    const float* fc_w = (const float*)d_in[6];
    float* out = (float*)d_out;

    fused_kernel<<<MU / 32, 1024>>>(x, fc_w, mask, out);
}